// round 10
// baseline (speedup 1.0000x reference)
#include <cuda_runtime.h>
#include <cuda_bf16.h>

// Shapes (fixed by setup_inputs): B=32, T=512, C=T-1=511, K=8, S=8, d=300
#define BB 32
#define CC 511
#define KK 8
#define SS 8
#define DD 300
#define D4 75      // DD/4 float4 per row
#define D2 150     // DD/2 float2 per row
#define TILE_C 32
#define NSPLIT 16  // ceil(511/32); must be power of 2 for wrapping counter
#define RSQRT300 0.057735026918962576f

// Scratch (device globals; no allocation allowed)
__device__ float g_pden[BB * NSPLIT * KK];        // partial sum of exp(a)
__device__ float g_mpart[BB * NSPLIT * KK * DD];  // partial unnormalized m'
__device__ unsigned g_cnt[BB];                    // wrapping completion counters

// ---------------------------------------------------------------------------
// Single fused kernel. grid (NSPLIT=16, B=32) = 512 blocks, block 256.
// Phases A/B identical to the proven R5 structure (36.5us, DRAM 56%).
// After phase B, each block arrives on g_cnt[b]; the 16th arrival for b
// (wrapping counter -- graph-replay safe, no reset race) computes the
// cosine similarities for all 8 k from the L2-resident partials, then the
// softmax/argmax/pooled-copy epilogue. No second kernel launch.
// ---------------------------------------------------------------------------
__global__ __launch_bounds__(256) void k_main(const float* __restrict__ ctx,
                                              const float* __restrict__ center,
                                              float* __restrict__ out) {
    const int b = blockIdx.y;
    const int tile = blockIdx.x;
    __shared__ float4 cen[KK * D4];        // 9600 B
    __shared__ float4 vt[TILE_C * D4];     // 38400 B
    __shared__ float ew[KK][TILE_C];       // 1024 B

    {
        const float4* cg = reinterpret_cast<const float4*>(center + (size_t)b * KK * DD);
        for (int i = threadIdx.x; i < KK * D4; i += blockDim.x) cen[i] = cg[i];
    }
    __syncthreads();

    const int w = threadIdx.x >> 5;
    const int lane = threadIdx.x & 31;
    const int j0 = lane, j1 = lane + 32, j2 = lane + 64;
    const bool p2 = (j2 < D4);

    const int c0 = tile * TILE_C;
    int cn = CC - c0; if (cn > TILE_C) cn = TILE_C;

    // ---- Phase A: warp per c; v=mean_s -> smem; fused dots, serial per-k ----
    for (int ci = w; ci < cn; ci += 8) {
        const int c = c0 + ci;
        const float4* p = reinterpret_cast<const float4*>(ctx) + (size_t)(b * CC + c) * (SS * D4);
        float4 a0 = {0.f, 0.f, 0.f, 0.f}, a1 = a0, a2 = a0;
#pragma unroll
        for (int s = 0; s < SS; s++) {
            const float4* ps = p + s * D4;
            float4 x0 = ps[j0];
            float4 x1 = ps[j1];
            a0.x += x0.x; a0.y += x0.y; a0.z += x0.z; a0.w += x0.w;
            a1.x += x1.x; a1.y += x1.y; a1.z += x1.z; a1.w += x1.w;
            if (p2) {
                float4 x2 = ps[j2];
                a2.x += x2.x; a2.y += x2.y; a2.z += x2.z; a2.w += x2.w;
            }
        }
        const float sc = 1.0f / (float)SS;
        a0.x *= sc; a0.y *= sc; a0.z *= sc; a0.w *= sc;
        a1.x *= sc; a1.y *= sc; a1.z *= sc; a1.w *= sc;
        a2.x *= sc; a2.y *= sc; a2.z *= sc; a2.w *= sc;

        vt[ci * D4 + j0] = a0;
        vt[ci * D4 + j1] = a1;
        if (p2) vt[ci * D4 + j2] = a2;

#pragma unroll
        for (int k = 0; k < KK; k++) {
            float4 c0v = cen[k * D4 + j0];
            float4 c1v = cen[k * D4 + j1];
            float t = a0.x * c0v.x + a0.y * c0v.y + a0.z * c0v.z + a0.w * c0v.w
                    + a1.x * c1v.x + a1.y * c1v.y + a1.z * c1v.z + a1.w * c1v.w;
            if (p2) {
                float4 c2v = cen[k * D4 + j2];
                t += a2.x * c2v.x + a2.y * c2v.y + a2.z * c2v.z + a2.w * c2v.w;
            }
#pragma unroll
            for (int off = 16; off > 0; off >>= 1)
                t += __shfl_xor_sync(0xffffffffu, t, off);
            if (lane == 0)
                ew[k][ci] = __expf(t * RSQRT300);
        }
    }
    __syncthreads();

    // ---- pden partials ----
    if (threadIdx.x < KK) {
        const int k = threadIdx.x;
        float s = 0.f;
        for (int cc = 0; cc < cn; cc++) s += ew[k][cc];
        g_pden[(b * NSPLIT + tile) * KK + k] = s;
    }

    // ---- Phase B ----
    {
        const int t = threadIdx.x;
        if (t < D2) {
            float2 acc[KK];
#pragma unroll
            for (int k = 0; k < KK; k++) acc[k] = make_float2(0.f, 0.f);

            const float2* vf = reinterpret_cast<const float2*>(vt);
#pragma unroll 4
            for (int cc = 0; cc < cn; cc++) {
                float2 v2 = vf[cc * D2 + t];
#pragma unroll
                for (int k = 0; k < KK; k++) {
                    float al = ew[k][cc];
                    acc[k].x += al * v2.x;
                    acc[k].y += al * v2.y;
                }
            }
            float2* mp = reinterpret_cast<float2*>(g_mpart) + (size_t)((b * NSPLIT + tile) * KK) * D2;
#pragma unroll
            for (int k = 0; k < KK; k++) mp[k * D2 + t] = acc[k];
        }
    }

    // ---- Arrival: last tile-block of this b runs the epilogue ----
    __syncthreads();
    __shared__ int slast;
    if (threadIdx.x == 0) {
        __threadfence();   // publish this block's mpart/pden (release)
        unsigned old = atomicAdd(&g_cnt[b], 1u);
        slast = ((old & (NSPLIT - 1)) == (NSPLIT - 1)) ? 1 : 0;
    }
    __syncthreads();
    if (!slast) return;

    // ---- Epilogue (one block per b): similarity for all 8 k, warp per k ----
    __shared__ float ssv[KK];
    __shared__ float sq[KK];
    __shared__ int sidx;
    {
        const int k = w;   // 8 warps = 8 senses
        float num = 0.f, n1 = 0.f, n2 = 0.f;
        const float2* cp2 = reinterpret_cast<const float2*>(center + (size_t)(b * KK + k) * DD);
#pragma unroll
        for (int it = 0; it < 5; it++) {
            const int j = lane + it * 32;
            if (j < D2) {
                float2 cv = cp2[j];
                float2 mm = make_float2(0.f, 0.f);
#pragma unroll
                for (int s = 0; s < NSPLIT; s++) {
                    const float2* mp = reinterpret_cast<const float2*>(g_mpart)
                                     + (size_t)((b * NSPLIT + s) * KK + k) * D2;
                    float2 x = __ldcg(mp + j);   // bypass stale L1
                    mm.x += x.x; mm.y += x.y;
                }
                num += cv.x * mm.x + cv.y * mm.y;
                n1  += cv.x * cv.x + cv.y * cv.y;
                n2  += mm.x * mm.x + mm.y * mm.y;
            }
        }
#pragma unroll
        for (int off = 16; off > 0; off >>= 1) {
            num += __shfl_xor_sync(0xffffffffu, num, off);
            n1  += __shfl_xor_sync(0xffffffffu, n1, off);
            n2  += __shfl_xor_sync(0xffffffffu, n2, off);
        }
        if (lane == 0) {
            float dsum = 0.f;
#pragma unroll
            for (int s = 0; s < NSPLIT; s++)
                dsum += __ldcg(&g_pden[(b * NSPLIT + s) * KK + k]);
            float invd = 1.0f / dsum;
            float d1 = fmaxf(sqrtf(n1), 1e-8f);
            float d2 = fmaxf(sqrtf(n2) * invd, 1e-8f);
            ssv[k] = (num * invd) / (d1 * d2);
        }
    }
    __syncthreads();

    if (threadIdx.x == 0) {
        float mx = ssv[0]; int id = 0;
#pragma unroll
        for (int i = 1; i < KK; i++)
            if (ssv[i] > mx) { mx = ssv[i]; id = i; }
        float den = 0.f;
#pragma unroll
        for (int i = 0; i < KK; i++) den += __expf(ssv[i] - mx);
        float invden = 1.0f / den;
#pragma unroll
        for (int i = 0; i < KK; i++) sq[i] = __expf(ssv[i] - mx) * invden;
        sidx = id;
    }
    __syncthreads();

    if (threadIdx.x < KK)
        out[BB * DD + b * KK + threadIdx.x] = sq[threadIdx.x];
    if (threadIdx.x < D4) {
        const float4* src = reinterpret_cast<const float4*>(center + (size_t)(b * KK + sidx) * DD);
        float4* dst = reinterpret_cast<float4*>(out + (size_t)b * DD);
        dst[threadIdx.x] = src[threadIdx.x];
    }
}

// ---------------------------------------------------------------------------
extern "C" void kernel_launch(void* const* d_in, const int* in_sizes, int n_in,
                              void* d_out, int out_size) {
    // inputs: 0 center_pos(i32), 1 query_token_ids(i32) -- both mathematically dead
    //         2 center_sense_embeddings f32 [32,8,300]
    //         3 context_sense_embeddings f32 [32,511,8,300]
    const float* center = (const float*)d_in[2];
    const float* ctx    = (const float*)d_in[3];
    float* out = (float*)d_out;

    k_main<<<dim3(NSPLIT, BB), 256>>>(ctx, center, out);
}